// round 2
// baseline (speedup 1.0000x reference)
#include <cuda_runtime.h>
#include <math.h>

#define B_  2
#define S_  2048
#define D_  1024
#define H_  16
#define HD_ 64

// ---------------- scratch (no allocs allowed) ----------------
__device__ float g_q[B_*H_*S_*HD_];
__device__ float g_k[B_*H_*S_*HD_];
__device__ float g_v[B_*H_*S_*HD_];
__device__ float g_cos[S_*(HD_/2)];
__device__ float g_sin[S_*(HD_/2)];

// ---------------- RoPE table (fp64 for accuracy) ----------------
__global__ void rope_table_kernel() {
    int idx = blockIdx.x * blockDim.x + threadIdx.x;
    if (idx < S_ * (HD_/2)) {
        int s = idx >> 5;       // HD_/2 = 32 entries per position
        int p = idx & 31;
        double theta = pow(10000.0, -(double)p / 32.0);
        double ang = (double)s * theta;
        g_cos[idx] = (float)cos(ang);
        g_sin[idx] = (float)sin(ang);
    }
}

// ---------------- QKV GEMM: out = x @ W^T + b, fused RoPE ----------------
// 128x128 tile, BK=8, 256 threads, 8x8 microtile.
// blockIdx.z: 0=Q, 1=K, 2=V. Writes [B,H,S,HD].
__global__ __launch_bounds__(256) void qkv_gemm_kernel(
    const float* __restrict__ x,
    const float* __restrict__ wq, const float* __restrict__ bq,
    const float* __restrict__ wk, const float* __restrict__ bk,
    const float* __restrict__ wv, const float* __restrict__ bv)
{
    const int mat = blockIdx.z;
    const float* __restrict__ W    = (mat==0) ? wq : (mat==1 ? wk : wv);
    const float* __restrict__ bias = (mat==0) ? bq : (mat==1 ? bk : bv);
    float* out = (mat==0) ? g_q : (mat==1 ? g_k : g_v);

    __shared__ float As[8][128];
    __shared__ float Bs[8][128];

    const int tid = threadIdx.x;
    const int tx  = tid & 15;
    const int ty  = tid >> 4;
    const int m0  = blockIdx.y * 128;
    const int n0  = blockIdx.x * 128;

    const int lrow = tid >> 1;          // 0..127
    const int lcol = (tid & 1) * 4;     // 0 or 4

    const float* aptr = x + (size_t)(m0 + lrow) * D_ + lcol;
    const float* bptr = W + (size_t)(n0 + lrow) * D_ + lcol;

    float acc[8][8];
    #pragma unroll
    for (int i = 0; i < 8; i++)
        #pragma unroll
        for (int j = 0; j < 8; j++) acc[i][j] = 0.f;

    for (int k0 = 0; k0 < D_; k0 += 8) {
        float4 a4 = *(const float4*)(aptr + k0);
        float4 b4 = *(const float4*)(bptr + k0);
        As[lcol+0][lrow] = a4.x; As[lcol+1][lrow] = a4.y;
        As[lcol+2][lrow] = a4.z; As[lcol+3][lrow] = a4.w;
        Bs[lcol+0][lrow] = b4.x; Bs[lcol+1][lrow] = b4.y;
        Bs[lcol+2][lrow] = b4.z; Bs[lcol+3][lrow] = b4.w;
        __syncthreads();
        #pragma unroll
        for (int kk = 0; kk < 8; kk++) {
            float a[8], b[8];
            *(float4*)&a[0] = *(const float4*)&As[kk][ty*8];
            *(float4*)&a[4] = *(const float4*)&As[kk][ty*8+4];
            *(float4*)&b[0] = *(const float4*)&Bs[kk][tx*8];
            *(float4*)&b[4] = *(const float4*)&Bs[kk][tx*8+4];
            #pragma unroll
            for (int i = 0; i < 8; i++)
                #pragma unroll
                for (int j = 0; j < 8; j++)
                    acc[i][j] += a[i] * b[j];
        }
        __syncthreads();
    }

    // epilogue: bias + (RoPE for Q/K), scatter to [B,H,S,HD]
    #pragma unroll
    for (int i = 0; i < 8; i++) {
        int m  = m0 + ty*8 + i;
        int b_ = m >> 11;          // /S_
        int s  = m & (S_ - 1);
        if (mat < 2) {
            #pragma unroll
            for (int jp = 0; jp < 4; jp++) {
                int n = n0 + tx*8 + 2*jp;
                float xr = acc[i][2*jp]   + bias[n];
                float xi = acc[i][2*jp+1] + bias[n+1];
                int h = n >> 6;
                int d = n & 63;
                int p = d >> 1;
                float cs = g_cos[s*32 + p];
                float sn = g_sin[s*32 + p];
                float* dst = out + ((((size_t)b_*H_ + h)*S_ + s)*HD_ + d);
                dst[0] = xr*cs - xi*sn;
                dst[1] = xr*sn + xi*cs;
            }
        } else {
            #pragma unroll
            for (int j = 0; j < 8; j++) {
                int n = n0 + tx*8 + j;
                int h = n >> 6;
                int d = n & 63;
                out[(((size_t)b_*H_ + h)*S_ + s)*HD_ + d] = acc[i][j] + bias[n];
            }
        }
    }
}

// ---------------- Flash attention ----------------
// Block: 64 queries of one (b,h). 256 threads as 16x16, 4x4 microtiles.
// smem: Q[64][64] | K[64][65] | V[64][65] | P[64][64]
#define KS_STRIDE 65
#define ATTN_SMEM_FLOATS (64*64 + 64*KS_STRIDE + 64*KS_STRIDE + 64*64)
#define ATTN_SMEM_BYTES  (ATTN_SMEM_FLOATS * 4)

__global__ __launch_bounds__(256) void attn_kernel(float* __restrict__ out)
{
    extern __shared__ float sm[];
    float* Qs = sm;                       // [64][64]
    float* Ks = Qs + 64*64;               // [64][65]
    float* Vs = Ks + 64*KS_STRIDE;        // [64][65]
    float* Ps = Vs + 64*KS_STRIDE;        // [64][64]

    const int tid = threadIdx.x;
    const int tx  = tid & 15;
    const int ty  = tid >> 4;
    const int q0  = blockIdx.x * 64;
    const int h   = blockIdx.y;
    const int b   = blockIdx.z;

    const float* qbase = g_q + (((size_t)b*H_ + h)*S_) * HD_;
    const float* kbase = g_k + (((size_t)b*H_ + h)*S_) * HD_;
    const float* vbase = g_v + (((size_t)b*H_ + h)*S_) * HD_;

    const float scale = 0.125f;  // 1/sqrt(64)

    // Load Q tile, pre-scaled
    #pragma unroll
    for (int r = 0; r < 4; r++) {
        int f = r*256 + tid;   // float4 index in 64x64 tile
        float4 v4 = *(const float4*)(qbase + (size_t)q0*64 + f*4);
        v4.x *= scale; v4.y *= scale; v4.z *= scale; v4.w *= scale;
        *(float4*)(Qs + f*4) = v4;
    }

    float m_i[4], l_i[4], o[4][4];
    #pragma unroll
    for (int i = 0; i < 4; i++) {
        m_i[i] = -INFINITY; l_i[i] = 0.f;
        #pragma unroll
        for (int j = 0; j < 4; j++) o[i][j] = 0.f;
    }

    for (int kt = 0; kt < S_/64; kt++) {
        __syncthreads();   // prior-iter P/V reads done
        // load K,V tiles (pad stride 65)
        #pragma unroll
        for (int r = 0; r < 4; r++) {
            int f   = r*256 + tid;
            int row = f >> 4;
            int c   = (f & 15) * 4;
            float4 kv = *(const float4*)(kbase + (size_t)kt*4096 + f*4);
            Ks[row*KS_STRIDE + c+0] = kv.x; Ks[row*KS_STRIDE + c+1] = kv.y;
            Ks[row*KS_STRIDE + c+2] = kv.z; Ks[row*KS_STRIDE + c+3] = kv.w;
            float4 vv = *(const float4*)(vbase + (size_t)kt*4096 + f*4);
            Vs[row*KS_STRIDE + c+0] = vv.x; Vs[row*KS_STRIDE + c+1] = vv.y;
            Vs[row*KS_STRIDE + c+2] = vv.z; Vs[row*KS_STRIDE + c+3] = vv.w;
        }
        __syncthreads();

        // scores: S = Q K^T (Q pre-scaled)
        float sc[4][4];
        #pragma unroll
        for (int i = 0; i < 4; i++)
            #pragma unroll
            for (int j = 0; j < 4; j++) sc[i][j] = 0.f;
        #pragma unroll 8
        for (int d = 0; d < 64; d++) {
            float a0 = Qs[(4*ty+0)*64 + d];
            float a1 = Qs[(4*ty+1)*64 + d];
            float a2 = Qs[(4*ty+2)*64 + d];
            float a3 = Qs[(4*ty+3)*64 + d];
            float b0 = Ks[(4*tx+0)*KS_STRIDE + d];
            float b1 = Ks[(4*tx+1)*KS_STRIDE + d];
            float b2 = Ks[(4*tx+2)*KS_STRIDE + d];
            float b3 = Ks[(4*tx+3)*KS_STRIDE + d];
            sc[0][0] += a0*b0; sc[0][1] += a0*b1; sc[0][2] += a0*b2; sc[0][3] += a0*b3;
            sc[1][0] += a1*b0; sc[1][1] += a1*b1; sc[1][2] += a1*b2; sc[1][3] += a1*b3;
            sc[2][0] += a2*b0; sc[2][1] += a2*b1; sc[2][2] += a2*b2; sc[2][3] += a2*b3;
            sc[3][0] += a3*b0; sc[3][1] += a3*b1; sc[3][2] += a3*b2; sc[3][3] += a3*b3;
        }

        // online softmax (16 threads per query row, shfl width 16)
        #pragma unroll
        for (int i = 0; i < 4; i++) {
            float mx = fmaxf(fmaxf(sc[i][0], sc[i][1]), fmaxf(sc[i][2], sc[i][3]));
            mx = fmaxf(mx, __shfl_xor_sync(0xffffffffu, mx, 1, 16));
            mx = fmaxf(mx, __shfl_xor_sync(0xffffffffu, mx, 2, 16));
            mx = fmaxf(mx, __shfl_xor_sync(0xffffffffu, mx, 4, 16));
            mx = fmaxf(mx, __shfl_xor_sync(0xffffffffu, mx, 8, 16));
            float mn = fmaxf(m_i[i], mx);
            float c  = __expf(m_i[i] - mn);   // exp(-inf)=0 on first tile
            m_i[i] = mn;
            l_i[i] *= c;
            o[i][0] *= c; o[i][1] *= c; o[i][2] *= c; o[i][3] *= c;
            float rs = 0.f;
            #pragma unroll
            for (int j = 0; j < 4; j++) {
                sc[i][j] = __expf(sc[i][j] - mn);
                rs += sc[i][j];
            }
            rs += __shfl_xor_sync(0xffffffffu, rs, 1, 16);
            rs += __shfl_xor_sync(0xffffffffu, rs, 2, 16);
            rs += __shfl_xor_sync(0xffffffffu, rs, 4, 16);
            rs += __shfl_xor_sync(0xffffffffu, rs, 8, 16);
            l_i[i] += rs;
            Ps[(4*ty+i)*64 + 4*tx+0] = sc[i][0];
            Ps[(4*ty+i)*64 + 4*tx+1] = sc[i][1];
            Ps[(4*ty+i)*64 + 4*tx+2] = sc[i][2];
            Ps[(4*ty+i)*64 + 4*tx+3] = sc[i][3];
        }
        __syncthreads();

        // O += P @ V
        #pragma unroll 8
        for (int k = 0; k < 64; k++) {
            float p0 = Ps[(4*ty+0)*64 + k];
            float p1 = Ps[(4*ty+1)*64 + k];
            float p2 = Ps[(4*ty+2)*64 + k];
            float p3 = Ps[(4*ty+3)*64 + k];
            float v0 = Vs[k*KS_STRIDE + 4*tx+0];
            float v1 = Vs[k*KS_STRIDE + 4*tx+1];
            float v2 = Vs[k*KS_STRIDE + 4*tx+2];
            float v3 = Vs[k*KS_STRIDE + 4*tx+3];
            o[0][0] += p0*v0; o[0][1] += p0*v1; o[0][2] += p0*v2; o[0][3] += p0*v3;
            o[1][0] += p1*v0; o[1][1] += p1*v1; o[1][2] += p1*v2; o[1][3] += p1*v3;
            o[2][0] += p2*v0; o[2][1] += p2*v1; o[2][2] += p2*v2; o[2][3] += p2*v3;
            o[3][0] += p3*v0; o[3][1] += p3*v1; o[3][2] += p3*v2; o[3][3] += p3*v3;
        }
    }

    // write out [B,S,D]
    #pragma unroll
    for (int i = 0; i < 4; i++) {
        float inv = 1.f / l_i[i];
        int s = q0 + 4*ty + i;
        float* dst = out + ((size_t)b*S_ + s)*D_ + h*HD_ + 4*tx;
        dst[0] = o[i][0]*inv;
        dst[1] = o[i][1]*inv;
        dst[2] = o[i][2]*inv;
        dst[3] = o[i][3]*inv;
    }
}

// ---------------- launch ----------------
extern "C" void kernel_launch(void* const* d_in, const int* in_sizes, int n_in,
                              void* d_out, int out_size) {
    const float* x    = (const float*)d_in[0];
    const float* wq_w = (const float*)d_in[1];
    const float* wq_b = (const float*)d_in[2];
    const float* wk_w = (const float*)d_in[3];
    const float* wk_b = (const float*)d_in[4];
    const float* wv_w = (const float*)d_in[5];
    const float* wv_b = (const float*)d_in[6];
    float* out = (float*)d_out;

    rope_table_kernel<<<(S_*(HD_/2) + 255)/256, 256>>>();

    dim3 gg(D_/128, (B_*S_)/128, 3);   // 8 x 32 x 3
    qkv_gemm_kernel<<<gg, 256>>>(x, wq_w, wq_b, wk_w, wk_b, wv_w, wv_b);

    cudaFuncSetAttribute(attn_kernel,
                         cudaFuncAttributeMaxDynamicSharedMemorySize,
                         ATTN_SMEM_BYTES);
    dim3 ga(S_/64, H_, B_);            // 32 x 16 x 2
    attn_kernel<<<ga, 256, ATTN_SMEM_BYTES>>>(out);
}

// round 3
// speedup vs baseline: 2.7914x; 2.7914x over previous
#include <cuda_runtime.h>
#include <math.h>

#define B_  2
#define S_  2048
#define D_  1024
#define H_  16
#define HD_ 64

// ---------------- scratch (no allocs allowed) ----------------
__device__ float g_q[B_*H_*S_*HD_];
__device__ float g_k[B_*H_*S_*HD_];
__device__ float g_v[B_*H_*S_*HD_];
__device__ float g_cos[S_*(HD_/2)];
__device__ float g_sin[S_*(HD_/2)];

// ---------------- helpers ----------------
__device__ __forceinline__ unsigned f2tf(float f) {
    unsigned u;
    asm("cvt.rna.tf32.f32 %0, %1;" : "=r"(u) : "f"(f));
    return u;
}

__device__ __forceinline__ void mma8(float* c, const unsigned* a, const unsigned* b) {
    asm volatile(
        "mma.sync.aligned.m16n8k8.row.col.f32.tf32.tf32.f32 "
        "{%0,%1,%2,%3},{%4,%5,%6,%7},{%8,%9},{%0,%1,%2,%3};"
        : "+f"(c[0]), "+f"(c[1]), "+f"(c[2]), "+f"(c[3])
        : "r"(a[0]), "r"(a[1]), "r"(a[2]), "r"(a[3]),
          "r"(b[0]), "r"(b[1]));
}

// ---------------- RoPE table (fp64 for accuracy) ----------------
__global__ void rope_table_kernel() {
    int idx = blockIdx.x * blockDim.x + threadIdx.x;
    if (idx < S_ * (HD_/2)) {
        int s = idx >> 5;
        int p = idx & 31;
        double theta = pow(10000.0, -(double)p / 32.0);
        double ang = (double)s * theta;
        g_cos[idx] = (float)cos(ang);
        g_sin[idx] = (float)sin(ang);
    }
}

// ---------------- QKV GEMM (tf32 mma): out = x @ W^T + b, fused RoPE ----------------
// 128x128 tile, BK=16, 256 threads = 8 warps, warp tile 64x32 (4 m16 x 4 n8).
#define GSTR 20   // smem row stride (floats): 16 + 4 pad -> conflict-free frags

__global__ __launch_bounds__(256, 2) void qkv_gemm_kernel(
    const float* __restrict__ x,
    const float* __restrict__ wq, const float* __restrict__ bq,
    const float* __restrict__ wk, const float* __restrict__ bk,
    const float* __restrict__ wv, const float* __restrict__ bv)
{
    const int mat = blockIdx.z;
    const float* __restrict__ W    = (mat==0) ? wq : (mat==1 ? wk : wv);
    const float* __restrict__ bias = (mat==0) ? bq : (mat==1 ? bk : bv);
    float* out = (mat==0) ? g_q : (mat==1 ? g_k : g_v);

    __shared__ unsigned As[128*GSTR];
    __shared__ unsigned Bs[128*GSTR];

    const int tid  = threadIdx.x;
    const int warp = tid >> 5;
    const int lane = tid & 31;
    const int g    = lane >> 2;
    const int tg   = lane & 3;
    const int wm   = warp & 1;     // 0..1 -> m offset 0/64
    const int wn   = warp >> 1;    // 0..3 -> n offset 0/32/64/96

    const int m0 = blockIdx.y * 128;
    const int n0 = blockIdx.x * 128;

    // loader mapping: 512 float4 per tile, 2 per thread
    int am[2], ac[2];
    {
        int f0 = tid;       am[0] = f0 >> 2; ac[0] = (f0 & 3) * 4;
        int f1 = tid + 256; am[1] = f1 >> 2; ac[1] = (f1 & 3) * 4;
    }
    const float* aG[2] = { x + (size_t)(m0 + am[0])*D_ + ac[0],
                           x + (size_t)(m0 + am[1])*D_ + ac[1] };
    const float* bG[2] = { W + (size_t)(n0 + am[0])*D_ + ac[0],
                           W + (size_t)(n0 + am[1])*D_ + ac[1] };

    float acc[4][4][4];
    #pragma unroll
    for (int i = 0; i < 4; i++)
        #pragma unroll
        for (int j = 0; j < 4; j++)
            #pragma unroll
            for (int q = 0; q < 4; q++) acc[i][j][q] = 0.f;

    float4 pa[2], pb[2];
    pa[0] = *(const float4*)(aG[0]); pa[1] = *(const float4*)(aG[1]);
    pb[0] = *(const float4*)(bG[0]); pb[1] = *(const float4*)(bG[1]);

    for (int k0 = 0; k0 < D_; k0 += 16) {
        // STS with tf32 convert
        #pragma unroll
        for (int i = 0; i < 2; i++) {
            uint4 ua = { f2tf(pa[i].x), f2tf(pa[i].y), f2tf(pa[i].z), f2tf(pa[i].w) };
            uint4 ub = { f2tf(pb[i].x), f2tf(pb[i].y), f2tf(pb[i].z), f2tf(pb[i].w) };
            *(uint4*)&As[am[i]*GSTR + ac[i]] = ua;
            *(uint4*)&Bs[am[i]*GSTR + ac[i]] = ub;
        }
        __syncthreads();

        if (k0 + 16 < D_) {
            pa[0] = *(const float4*)(aG[0] + k0 + 16);
            pa[1] = *(const float4*)(aG[1] + k0 + 16);
            pb[0] = *(const float4*)(bG[0] + k0 + 16);
            pb[1] = *(const float4*)(bG[1] + k0 + 16);
        }

        #pragma unroll
        for (int kk = 0; kk < 2; kk++) {
            const int k = kk * 8;
            unsigned af[4][4], bf[4][2];
            #pragma unroll
            for (int mt = 0; mt < 4; mt++) {
                int rm = wm*64 + mt*16;
                af[mt][0] = As[(rm+g  )*GSTR + k + tg];
                af[mt][1] = As[(rm+g+8)*GSTR + k + tg];
                af[mt][2] = As[(rm+g  )*GSTR + k + tg + 4];
                af[mt][3] = As[(rm+g+8)*GSTR + k + tg + 4];
            }
            #pragma unroll
            for (int nt = 0; nt < 4; nt++) {
                int cn = wn*32 + nt*8;
                bf[nt][0] = Bs[(cn+g)*GSTR + k + tg];
                bf[nt][1] = Bs[(cn+g)*GSTR + k + tg + 4];
            }
            #pragma unroll
            for (int mt = 0; mt < 4; mt++)
                #pragma unroll
                for (int nt = 0; nt < 4; nt++)
                    mma8(acc[mt][nt], af[mt], bf[nt]);
        }
        __syncthreads();
    }

    // epilogue: bias + (RoPE for Q/K), scatter to [B,H,S,HD]
    #pragma unroll
    for (int mt = 0; mt < 4; mt++) {
        #pragma unroll
        for (int half = 0; half < 2; half++) {
            int r  = m0 + wm*64 + mt*16 + g + half*8;
            int b_ = r >> 11;
            int s  = r & (S_ - 1);
            #pragma unroll
            for (int nt = 0; nt < 4; nt++) {
                int n  = n0 + wn*32 + nt*8 + 2*tg;   // even
                float c0 = acc[mt][nt][half*2]   + bias[n];
                float c1 = acc[mt][nt][half*2+1] + bias[n+1];
                int h = n >> 6;
                int d = n & 63;
                float* dst = out + ((((size_t)b_*H_ + h)*S_ + s)*HD_ + d);
                if (mat < 2) {
                    int p = d >> 1;
                    float cs = g_cos[s*32 + p];
                    float sn = g_sin[s*32 + p];
                    float2 v = { c0*cs - c1*sn, c0*sn + c1*cs };
                    *(float2*)dst = v;
                } else {
                    float2 v = { c0, c1 };
                    *(float2*)dst = v;
                }
            }
        }
    }
}

// ---------------- Flash attention (tf32 mma) ----------------
// Block: 128 queries of one (b,h). 8 warps, each owns a 16-row slab.
// K tile 64 keys. Q frags register-resident; P re-fragmented via smem.
#define PSTR 68   // P / Q-stage stride (floats)
#define KSTR 68   // K stride
#define VSTR 72   // V stride (8tg+g bank pattern -> conflict-free)
#define ATTN_SMEM_WORDS (128*PSTR + 64*KSTR + 64*VSTR)
#define ATTN_SMEM_BYTES (ATTN_SMEM_WORDS * 4)

__global__ __launch_bounds__(256, 1) void attn_kernel(float* __restrict__ out)
{
    extern __shared__ unsigned sm[];
    unsigned* Ps = sm;                 // [128][PSTR]
    unsigned* Ks = Ps + 128*PSTR;      // [64][KSTR]
    unsigned* Vs = Ks + 64*KSTR;       // [64][VSTR]

    const int tid  = threadIdx.x;
    const int warp = tid >> 5;
    const int lane = tid & 31;
    const int g    = lane >> 2;
    const int tg   = lane & 3;
    const int qr   = warp * 16;        // warp's row slab within tile

    const int q0 = blockIdx.x * 128;
    const int h  = blockIdx.y;
    const int b  = blockIdx.z;

    const float* qbase = g_q + (((size_t)b*H_ + h)*S_) * HD_;
    const float* kbase = g_k + (((size_t)b*H_ + h)*S_) * HD_;
    const float* vbase = g_v + (((size_t)b*H_ + h)*S_) * HD_;

    const float scale = 0.125f;

    // ---- stage Q (scaled, tf32) into Ps, build register fragments ----
    #pragma unroll
    for (int r = 0; r < 8; r++) {
        int f   = tid + 256*r;           // 0..2047 float4s
        int row = f >> 4;
        int col = (f & 15) * 4;
        float4 v = *(const float4*)(qbase + (size_t)(q0+row)*HD_ + col);
        uint4 u = { f2tf(v.x*scale), f2tf(v.y*scale), f2tf(v.z*scale), f2tf(v.w*scale) };
        *(uint4*)&Ps[row*PSTR + col] = u;
    }
    __syncthreads();

    unsigned qf[8][4];
    #pragma unroll
    for (int kk = 0; kk < 8; kk++) {
        qf[kk][0] = Ps[(qr+g  )*PSTR + kk*8 + tg];
        qf[kk][1] = Ps[(qr+g+8)*PSTR + kk*8 + tg];
        qf[kk][2] = Ps[(qr+g  )*PSTR + kk*8 + tg + 4];
        qf[kk][3] = Ps[(qr+g+8)*PSTR + kk*8 + tg + 4];
    }
    __syncthreads();   // everyone done reading Q before Ps is reused for P

    float o[8][4];
    #pragma unroll
    for (int nt = 0; nt < 8; nt++)
        #pragma unroll
        for (int q = 0; q < 4; q++) o[nt][q] = 0.f;
    float m0r = -INFINITY, m1r = -INFINITY, l0 = 0.f, l1 = 0.f;

    // K/V prefetch: 1024 float4 per tile, 4 per thread
    int krow[4], kcol[4];
    #pragma unroll
    for (int r = 0; r < 4; r++) {
        int f = tid + 256*r;
        krow[r] = f >> 4;
        kcol[r] = (f & 15) * 4;
    }
    float4 pk[4], pv[4];
    #pragma unroll
    for (int r = 0; r < 4; r++) {
        int off = (tid + 256*r) * 4;
        pk[r] = *(const float4*)(kbase + off);
        pv[r] = *(const float4*)(vbase + off);
    }

    for (int kt = 0; kt < S_/64; kt++) {
        __syncthreads();   // previous iter's Ks/Vs consumers done
        #pragma unroll
        for (int r = 0; r < 4; r++) {
            uint4 uk = { f2tf(pk[r].x), f2tf(pk[r].y), f2tf(pk[r].z), f2tf(pk[r].w) };
            uint4 uv = { f2tf(pv[r].x), f2tf(pv[r].y), f2tf(pv[r].z), f2tf(pv[r].w) };
            *(uint4*)&Ks[krow[r]*KSTR + kcol[r]] = uk;
            *(uint4*)&Vs[krow[r]*VSTR + kcol[r]] = uv;
        }
        __syncthreads();

        if (kt + 1 < S_/64) {
            #pragma unroll
            for (int r = 0; r < 4; r++) {
                int off = (kt+1)*4096 + (tid + 256*r) * 4;
                pk[r] = *(const float4*)(kbase + off);
                pv[r] = *(const float4*)(vbase + off);
            }
        }

        // ---- S = Q K^T ----
        float s[8][4];
        #pragma unroll
        for (int nt = 0; nt < 8; nt++)
            #pragma unroll
            for (int q = 0; q < 4; q++) s[nt][q] = 0.f;

        #pragma unroll
        for (int nt = 0; nt < 8; nt++) {
            #pragma unroll
            for (int kk = 0; kk < 8; kk++) {
                unsigned bfr[2];
                bfr[0] = Ks[(nt*8+g)*KSTR + kk*8 + tg];
                bfr[1] = Ks[(nt*8+g)*KSTR + kk*8 + tg + 4];
                mma8(s[nt], qf[kk], bfr);
            }
        }

        // ---- online softmax (rows r=qr+g and r+8) ----
        float mx0 = -INFINITY, mx1 = -INFINITY;
        #pragma unroll
        for (int nt = 0; nt < 8; nt++) {
            mx0 = fmaxf(mx0, fmaxf(s[nt][0], s[nt][1]));
            mx1 = fmaxf(mx1, fmaxf(s[nt][2], s[nt][3]));
        }
        mx0 = fmaxf(mx0, __shfl_xor_sync(0xffffffffu, mx0, 1));
        mx0 = fmaxf(mx0, __shfl_xor_sync(0xffffffffu, mx0, 2));
        mx1 = fmaxf(mx1, __shfl_xor_sync(0xffffffffu, mx1, 1));
        mx1 = fmaxf(mx1, __shfl_xor_sync(0xffffffffu, mx1, 2));

        float nm0 = fmaxf(m0r, mx0), nm1 = fmaxf(m1r, mx1);
        float f0 = __expf(m0r - nm0), f1 = __expf(m1r - nm1);
        m0r = nm0; m1r = nm1;

        float rs0 = 0.f, rs1 = 0.f;
        #pragma unroll
        for (int nt = 0; nt < 8; nt++) {
            s[nt][0] = __expf(s[nt][0] - nm0);
            s[nt][1] = __expf(s[nt][1] - nm0);
            s[nt][2] = __expf(s[nt][2] - nm1);
            s[nt][3] = __expf(s[nt][3] - nm1);
            rs0 += s[nt][0] + s[nt][1];
            rs1 += s[nt][2] + s[nt][3];
            o[nt][0] *= f0; o[nt][1] *= f0;
            o[nt][2] *= f1; o[nt][3] *= f1;
        }
        rs0 += __shfl_xor_sync(0xffffffffu, rs0, 1);
        rs0 += __shfl_xor_sync(0xffffffffu, rs0, 2);
        rs1 += __shfl_xor_sync(0xffffffffu, rs1, 1);
        rs1 += __shfl_xor_sync(0xffffffffu, rs1, 2);
        l0 = l0*f0 + rs0;
        l1 = l1*f1 + rs1;

        // ---- store P (tf32) to smem for re-fragmenting ----
        #pragma unroll
        for (int nt = 0; nt < 8; nt++) {
            Ps[(qr+g  )*PSTR + nt*8 + 2*tg    ] = f2tf(s[nt][0]);
            Ps[(qr+g  )*PSTR + nt*8 + 2*tg + 1] = f2tf(s[nt][1]);
            Ps[(qr+g+8)*PSTR + nt*8 + 2*tg    ] = f2tf(s[nt][2]);
            Ps[(qr+g+8)*PSTR + nt*8 + 2*tg + 1] = f2tf(s[nt][3]);
        }
        __syncwarp();

        // ---- O += P V ----
        #pragma unroll
        for (int kk = 0; kk < 8; kk++) {
            unsigned pf[4];
            pf[0] = Ps[(qr+g  )*PSTR + kk*8 + tg];
            pf[1] = Ps[(qr+g+8)*PSTR + kk*8 + tg];
            pf[2] = Ps[(qr+g  )*PSTR + kk*8 + tg + 4];
            pf[3] = Ps[(qr+g+8)*PSTR + kk*8 + tg + 4];
            #pragma unroll
            for (int nt = 0; nt < 8; nt++) {
                unsigned bfr[2];
                bfr[0] = Vs[(kk*8+tg  )*VSTR + nt*8 + g];
                bfr[1] = Vs[(kk*8+tg+4)*VSTR + nt*8 + g];
                mma8(o[nt], pf, bfr);
            }
        }
    }

    // ---- finalize + write out [B,S,D] ----
    float inv0 = 1.f / l0, inv1 = 1.f / l1;
    int sr0 = q0 + qr + g;
    int sr1 = sr0 + 8;
    #pragma unroll
    for (int nt = 0; nt < 8; nt++) {
        int d = nt*8 + 2*tg;
        float2 v0 = { o[nt][0]*inv0, o[nt][1]*inv0 };
        float2 v1 = { o[nt][2]*inv1, o[nt][3]*inv1 };
        *(float2*)(out + ((size_t)b*S_ + sr0)*D_ + h*HD_ + d) = v0;
        *(float2*)(out + ((size_t)b*S_ + sr1)*D_ + h*HD_ + d) = v1;
    }
}

// ---------------- launch ----------------
extern "C" void kernel_launch(void* const* d_in, const int* in_sizes, int n_in,
                              void* d_out, int out_size) {
    const float* x    = (const float*)d_in[0];
    const float* wq_w = (const float*)d_in[1];
    const float* wq_b = (const float*)d_in[2];
    const float* wk_w = (const float*)d_in[3];
    const float* wk_b = (const float*)d_in[4];
    const float* wv_w = (const float*)d_in[5];
    const float* wv_b = (const float*)d_in[6];
    float* out = (float*)d_out;

    rope_table_kernel<<<(S_*(HD_/2) + 255)/256, 256>>>();

    dim3 gg(D_/128, (B_*S_)/128, 3);
    qkv_gemm_kernel<<<gg, 256>>>(x, wq_w, wq_b, wk_w, wk_b, wv_w, wv_b);

    cudaFuncSetAttribute(attn_kernel,
                         cudaFuncAttributeMaxDynamicSharedMemorySize,
                         ATTN_SMEM_BYTES);
    dim3 ga(S_/128, H_, B_);
    attn_kernel<<<ga, 256, ATTN_SMEM_BYTES>>>(out);
}

// round 4
// speedup vs baseline: 2.9840x; 1.0690x over previous
#include <cuda_runtime.h>
#include <math.h>

#define B_  2
#define S_  2048
#define D_  1024
#define H_  16
#define HD_ 64

// ---------------- scratch (no allocs allowed) ----------------
__device__ float g_q[B_*H_*S_*HD_];
__device__ float g_k[B_*H_*S_*HD_];
__device__ float g_v[B_*H_*S_*HD_];
__device__ float g_cos[S_*(HD_/2)];
__device__ float g_sin[S_*(HD_/2)];

// ---------------- helpers ----------------
__device__ __forceinline__ unsigned f2tf(float f) {
    unsigned u;
    asm("cvt.rna.tf32.f32 %0, %1;" : "=r"(u) : "f"(f));
    return u;
}

__device__ __forceinline__ void mma8(float* c, const unsigned* a, const unsigned* b) {
    asm volatile(
        "mma.sync.aligned.m16n8k8.row.col.f32.tf32.tf32.f32 "
        "{%0,%1,%2,%3},{%4,%5,%6,%7},{%8,%9},{%0,%1,%2,%3};"
        : "+f"(c[0]), "+f"(c[1]), "+f"(c[2]), "+f"(c[3])
        : "r"(a[0]), "r"(a[1]), "r"(a[2]), "r"(a[3]),
          "r"(b[0]), "r"(b[1]));
}

__device__ __forceinline__ void cpa16(void* smem, const void* gmem) {
    unsigned s = (unsigned)__cvta_generic_to_shared(smem);
    asm volatile("cp.async.cg.shared.global [%0], [%1], 16;" :: "r"(s), "l"(gmem));
}
#define CPA_COMMIT() asm volatile("cp.async.commit_group;")
#define CPA_WAIT0()  asm volatile("cp.async.wait_group 0;")

// ---------------- RoPE table ----------------
__global__ void rope_table_kernel() {
    int idx = blockIdx.x * blockDim.x + threadIdx.x;
    if (idx < S_ * (HD_/2)) {
        int s = idx >> 5;
        int p = idx & 31;
        // theta = 10000^(-p/32) = 2^(-p*log2(10000)/32)
        double theta = exp2(-(double)p * (13.287712379549449 / 32.0));
        double ang = (double)s * theta;
        const double twopi = 6.283185307179586476925286766559;
        double r = ang - twopi * floor(ang / twopi);
        float fr = (float)r;
        float sn, cs;
        sincosf(fr, &sn, &cs);
        g_cos[idx] = cs;
        g_sin[idx] = sn;
    }
}

// ---------------- QKV GEMM (tf32 mma, double-buffered smem) ----------------
// 128x128 tile, BK=16, 256 threads = 8 warps, warp tile 64x32 (4 m16 x 4 n8).
#define GSTR 20

__global__ __launch_bounds__(256, 2) void qkv_gemm_kernel(
    const float* __restrict__ x,
    const float* __restrict__ wq, const float* __restrict__ bq,
    const float* __restrict__ wk, const float* __restrict__ bk,
    const float* __restrict__ wv, const float* __restrict__ bv)
{
    const int mat = blockIdx.z;
    const float* __restrict__ W    = (mat==0) ? wq : (mat==1 ? wk : wv);
    const float* __restrict__ bias = (mat==0) ? bq : (mat==1 ? bk : bv);
    float* out = (mat==0) ? g_q : (mat==1 ? g_k : g_v);

    __shared__ unsigned As[2][128*GSTR];
    __shared__ unsigned Bs[2][128*GSTR];

    const int tid  = threadIdx.x;
    const int warp = tid >> 5;
    const int lane = tid & 31;
    const int g    = lane >> 2;
    const int tg   = lane & 3;
    const int wm   = warp & 1;
    const int wn   = warp >> 1;

    const int m0 = blockIdx.y * 128;
    const int n0 = blockIdx.x * 128;

    int am[2], ac[2];
    {
        int f0 = tid;       am[0] = f0 >> 2; ac[0] = (f0 & 3) * 4;
        int f1 = tid + 256; am[1] = f1 >> 2; ac[1] = (f1 & 3) * 4;
    }
    const float* aG[2] = { x + (size_t)(m0 + am[0])*D_ + ac[0],
                           x + (size_t)(m0 + am[1])*D_ + ac[1] };
    const float* bG[2] = { W + (size_t)(n0 + am[0])*D_ + ac[0],
                           W + (size_t)(n0 + am[1])*D_ + ac[1] };

    float acc[4][4][4];
    #pragma unroll
    for (int i = 0; i < 4; i++)
        #pragma unroll
        for (int j = 0; j < 4; j++)
            #pragma unroll
            for (int q = 0; q < 4; q++) acc[i][j][q] = 0.f;

    // stage 0
    float4 pa[2], pb[2];
    #pragma unroll
    for (int i = 0; i < 2; i++) {
        pa[i] = *(const float4*)(aG[i]);
        pb[i] = *(const float4*)(bG[i]);
    }
    #pragma unroll
    for (int i = 0; i < 2; i++) {
        uint4 ua = { f2tf(pa[i].x), f2tf(pa[i].y), f2tf(pa[i].z), f2tf(pa[i].w) };
        uint4 ub = { f2tf(pb[i].x), f2tf(pb[i].y), f2tf(pb[i].z), f2tf(pb[i].w) };
        *(uint4*)&As[0][am[i]*GSTR + ac[i]] = ua;
        *(uint4*)&Bs[0][am[i]*GSTR + ac[i]] = ub;
    }
    __syncthreads();

    int cur = 0;
    for (int k0 = 0; k0 < D_; k0 += 16) {
        const bool more = (k0 + 16 < D_);
        if (more) {
            #pragma unroll
            for (int i = 0; i < 2; i++) {
                pa[i] = *(const float4*)(aG[i] + k0 + 16);
                pb[i] = *(const float4*)(bG[i] + k0 + 16);
            }
        }

        #pragma unroll
        for (int kk = 0; kk < 2; kk++) {
            const int k = kk * 8;
            unsigned af[4][4], bf[4][2];
            #pragma unroll
            for (int mt = 0; mt < 4; mt++) {
                int rm = wm*64 + mt*16;
                af[mt][0] = As[cur][(rm+g  )*GSTR + k + tg];
                af[mt][1] = As[cur][(rm+g+8)*GSTR + k + tg];
                af[mt][2] = As[cur][(rm+g  )*GSTR + k + tg + 4];
                af[mt][3] = As[cur][(rm+g+8)*GSTR + k + tg + 4];
            }
            #pragma unroll
            for (int nt = 0; nt < 4; nt++) {
                int cn = wn*32 + nt*8;
                bf[nt][0] = Bs[cur][(cn+g)*GSTR + k + tg];
                bf[nt][1] = Bs[cur][(cn+g)*GSTR + k + tg + 4];
            }
            #pragma unroll
            for (int mt = 0; mt < 4; mt++)
                #pragma unroll
                for (int nt = 0; nt < 4; nt++)
                    mma8(acc[mt][nt], af[mt], bf[nt]);
        }

        if (more) {
            #pragma unroll
            for (int i = 0; i < 2; i++) {
                uint4 ua = { f2tf(pa[i].x), f2tf(pa[i].y), f2tf(pa[i].z), f2tf(pa[i].w) };
                uint4 ub = { f2tf(pb[i].x), f2tf(pb[i].y), f2tf(pb[i].z), f2tf(pb[i].w) };
                *(uint4*)&As[cur^1][am[i]*GSTR + ac[i]] = ua;
                *(uint4*)&Bs[cur^1][am[i]*GSTR + ac[i]] = ub;
            }
        }
        __syncthreads();
        cur ^= 1;
    }

    // epilogue: bias + (RoPE for Q/K), scatter to [B,H,S,HD]
    #pragma unroll
    for (int mt = 0; mt < 4; mt++) {
        #pragma unroll
        for (int half = 0; half < 2; half++) {
            int r  = m0 + wm*64 + mt*16 + g + half*8;
            int b_ = r >> 11;
            int s  = r & (S_ - 1);
            #pragma unroll
            for (int nt = 0; nt < 4; nt++) {
                int n  = n0 + wn*32 + nt*8 + 2*tg;
                float c0 = acc[mt][nt][half*2]   + bias[n];
                float c1 = acc[mt][nt][half*2+1] + bias[n+1];
                int h = n >> 6;
                int d = n & 63;
                float* dst = out + ((((size_t)b_*H_ + h)*S_ + s)*HD_ + d);
                if (mat < 2) {
                    int p = d >> 1;
                    float cs = g_cos[s*32 + p];
                    float sn = g_sin[s*32 + p];
                    float2 v = { c0*cs - c1*sn, c0*sn + c1*cs };
                    *(float2*)dst = v;
                } else {
                    float2 v = { c0, c1 };
                    *(float2*)dst = v;
                }
            }
        }
    }
}

// ---------------- Flash attention (tf32 mma, cp.async K/V, occ 2) ----------------
// Block: 128 queries of one (b,h). 8 warps, each owns a 16-row slab.
// K tile 64 keys. K/V staged raw fp32 via cp.async, cvt at fragment load.
#define PSTR 68
#define KSTR 68
#define VSTR 72
#define ATTN_SMEM_WORDS (128*PSTR + 64*KSTR + 64*VSTR)
#define ATTN_SMEM_BYTES (ATTN_SMEM_WORDS * 4)

__global__ __launch_bounds__(256, 2) void attn_kernel(float* __restrict__ out)
{
    extern __shared__ unsigned sm[];
    unsigned* Ps = sm;                              // [128][PSTR] tf32
    float* Ksf   = (float*)(Ps + 128*PSTR);         // [64][KSTR]  fp32
    float* Vsf   = Ksf + 64*KSTR;                   // [64][VSTR]  fp32

    const int tid  = threadIdx.x;
    const int warp = tid >> 5;
    const int lane = tid & 31;
    const int g    = lane >> 2;
    const int tg   = lane & 3;
    const int qr   = warp * 16;

    const int q0 = blockIdx.x * 128;
    const int h  = blockIdx.y;
    const int b  = blockIdx.z;

    const float* qbase = g_q + (((size_t)b*H_ + h)*S_) * HD_;
    const float* kbase = g_k + (((size_t)b*H_ + h)*S_) * HD_;
    const float* vbase = g_v + (((size_t)b*H_ + h)*S_) * HD_;

    const float scale = 0.125f;

    // per-thread K/V copy mapping: 4 x 16B each
    int krow[4], kcol[4];
    #pragma unroll
    for (int r = 0; r < 4; r++) {
        int f = tid + 256*r;
        krow[r] = f >> 4;
        kcol[r] = (f & 15) * 4;
    }

    // kick off tile 0 K/V loads (overlaps Q staging)
    #pragma unroll
    for (int r = 0; r < 4; r++) {
        int off = (tid + 256*r) * 4;
        cpa16(&Ksf[krow[r]*KSTR + kcol[r]], kbase + off);
        cpa16(&Vsf[krow[r]*VSTR + kcol[r]], vbase + off);
    }
    CPA_COMMIT();

    // ---- stage Q (scaled, tf32) into Ps, build register fragments ----
    #pragma unroll
    for (int r = 0; r < 8; r++) {
        int f   = tid + 256*r;
        int row = f >> 4;
        int col = (f & 15) * 4;
        float4 v = *(const float4*)(qbase + (size_t)(q0+row)*HD_ + col);
        uint4 u = { f2tf(v.x*scale), f2tf(v.y*scale), f2tf(v.z*scale), f2tf(v.w*scale) };
        *(uint4*)&Ps[row*PSTR + col] = u;
    }
    __syncthreads();

    unsigned qf[8][4];
    #pragma unroll
    for (int kk = 0; kk < 8; kk++) {
        qf[kk][0] = Ps[(qr+g  )*PSTR + kk*8 + tg];
        qf[kk][1] = Ps[(qr+g+8)*PSTR + kk*8 + tg];
        qf[kk][2] = Ps[(qr+g  )*PSTR + kk*8 + tg + 4];
        qf[kk][3] = Ps[(qr+g+8)*PSTR + kk*8 + tg + 4];
    }
    __syncthreads();   // Q reads done before Ps reused for P

    float o[8][4];
    #pragma unroll
    for (int nt = 0; nt < 8; nt++)
        #pragma unroll
        for (int q = 0; q < 4; q++) o[nt][q] = 0.f;
    float m0r = -INFINITY, m1r = -INFINITY, l0 = 0.f, l1 = 0.f;

    for (int kt = 0; kt < S_/64; kt++) {
        CPA_WAIT0();
        __syncthreads();   // K/V tile ready everywhere

        // ---- S = Q K^T ----
        float s[8][4];
        #pragma unroll
        for (int nt = 0; nt < 8; nt++)
            #pragma unroll
            for (int q = 0; q < 4; q++) s[nt][q] = 0.f;

        #pragma unroll
        for (int nt = 0; nt < 8; nt++) {
            #pragma unroll
            for (int kk = 0; kk < 8; kk++) {
                unsigned bfr[2];
                bfr[0] = f2tf(Ksf[(nt*8+g)*KSTR + kk*8 + tg]);
                bfr[1] = f2tf(Ksf[(nt*8+g)*KSTR + kk*8 + tg + 4]);
                mma8(s[nt], qf[kk], bfr);
            }
        }

        // ---- online softmax ----
        float mx0 = -INFINITY, mx1 = -INFINITY;
        #pragma unroll
        for (int nt = 0; nt < 8; nt++) {
            mx0 = fmaxf(mx0, fmaxf(s[nt][0], s[nt][1]));
            mx1 = fmaxf(mx1, fmaxf(s[nt][2], s[nt][3]));
        }
        mx0 = fmaxf(mx0, __shfl_xor_sync(0xffffffffu, mx0, 1));
        mx0 = fmaxf(mx0, __shfl_xor_sync(0xffffffffu, mx0, 2));
        mx1 = fmaxf(mx1, __shfl_xor_sync(0xffffffffu, mx1, 1));
        mx1 = fmaxf(mx1, __shfl_xor_sync(0xffffffffu, mx1, 2));

        float nm0 = fmaxf(m0r, mx0), nm1 = fmaxf(m1r, mx1);
        float f0 = __expf(m0r - nm0), f1 = __expf(m1r - nm1);
        m0r = nm0; m1r = nm1;

        float rs0 = 0.f, rs1 = 0.f;
        #pragma unroll
        for (int nt = 0; nt < 8; nt++) {
            s[nt][0] = __expf(s[nt][0] - nm0);
            s[nt][1] = __expf(s[nt][1] - nm0);
            s[nt][2] = __expf(s[nt][2] - nm1);
            s[nt][3] = __expf(s[nt][3] - nm1);
            rs0 += s[nt][0] + s[nt][1];
            rs1 += s[nt][2] + s[nt][3];
            o[nt][0] *= f0; o[nt][1] *= f0;
            o[nt][2] *= f1; o[nt][3] *= f1;
        }
        rs0 += __shfl_xor_sync(0xffffffffu, rs0, 1);
        rs0 += __shfl_xor_sync(0xffffffffu, rs0, 2);
        rs1 += __shfl_xor_sync(0xffffffffu, rs1, 1);
        rs1 += __shfl_xor_sync(0xffffffffu, rs1, 2);
        l0 = l0*f0 + rs0;
        l1 = l1*f1 + rs1;

        // ---- store P (tf32) for re-fragmenting (within-warp only) ----
        #pragma unroll
        for (int nt = 0; nt < 8; nt++) {
            Ps[(qr+g  )*PSTR + nt*8 + 2*tg    ] = f2tf(s[nt][0]);
            Ps[(qr+g  )*PSTR + nt*8 + 2*tg + 1] = f2tf(s[nt][1]);
            Ps[(qr+g+8)*PSTR + nt*8 + 2*tg    ] = f2tf(s[nt][2]);
            Ps[(qr+g+8)*PSTR + nt*8 + 2*tg + 1] = f2tf(s[nt][3]);
        }
        __syncwarp();

        // ---- O += P V ----
        #pragma unroll
        for (int kk = 0; kk < 8; kk++) {
            unsigned pf[4];
            pf[0] = Ps[(qr+g  )*PSTR + kk*8 + tg];
            pf[1] = Ps[(qr+g+8)*PSTR + kk*8 + tg];
            pf[2] = Ps[(qr+g  )*PSTR + kk*8 + tg + 4];
            pf[3] = Ps[(qr+g+8)*PSTR + kk*8 + tg + 4];
            #pragma unroll
            for (int nt = 0; nt < 8; nt++) {
                unsigned bfr[2];
                bfr[0] = f2tf(Vsf[(kk*8+tg  )*VSTR + nt*8 + g]);
                bfr[1] = f2tf(Vsf[(kk*8+tg+4)*VSTR + nt*8 + g]);
                mma8(o[nt], pf, bfr);
            }
        }

        __syncthreads();   // all K/V consumers done before refill
        if (kt + 1 < S_/64) {
            const float* kb = kbase + (size_t)(kt+1)*4096;
            const float* vb = vbase + (size_t)(kt+1)*4096;
            #pragma unroll
            for (int r = 0; r < 4; r++) {
                int off = (tid + 256*r) * 4;
                cpa16(&Ksf[krow[r]*KSTR + kcol[r]], kb + off);
                cpa16(&Vsf[krow[r]*VSTR + kcol[r]], vb + off);
            }
            CPA_COMMIT();
        }
    }

    // ---- finalize + write out [B,S,D] ----
    float inv0 = 1.f / l0, inv1 = 1.f / l1;
    int sr0 = q0 + qr + g;
    int sr1 = sr0 + 8;
    #pragma unroll
    for (int nt = 0; nt < 8; nt++) {
        int d = nt*8 + 2*tg;
        float2 v0 = { o[nt][0]*inv0, o[nt][1]*inv0 };
        float2 v1 = { o[nt][2]*inv1, o[nt][3]*inv1 };
        *(float2*)(out + ((size_t)b*S_ + sr0)*D_ + h*HD_ + d) = v0;
        *(float2*)(out + ((size_t)b*S_ + sr1)*D_ + h*HD_ + d) = v1;
    }
}

// ---------------- launch ----------------
extern "C" void kernel_launch(void* const* d_in, const int* in_sizes, int n_in,
                              void* d_out, int out_size) {
    const float* x    = (const float*)d_in[0];
    const float* wq_w = (const float*)d_in[1];
    const float* wq_b = (const float*)d_in[2];
    const float* wk_w = (const float*)d_in[3];
    const float* wk_b = (const float*)d_in[4];
    const float* wv_w = (const float*)d_in[5];
    const float* wv_b = (const float*)d_in[6];
    float* out = (float*)d_out;

    rope_table_kernel<<<(S_*(HD_/2) + 255)/256, 256>>>();

    dim3 gg(D_/128, (B_*S_)/128, 3);
    qkv_gemm_kernel<<<gg, 256>>>(x, wq_w, wq_b, wk_w, wk_b, wv_w, wv_b);

    cudaFuncSetAttribute(attn_kernel,
                         cudaFuncAttributeMaxDynamicSharedMemorySize,
                         ATTN_SMEM_BYTES);
    dim3 ga(S_/128, H_, B_);
    attn_kernel<<<ga, 256, ATTN_SMEM_BYTES>>>(out);
}